// round 7
// baseline (speedup 1.0000x reference)
#include <cuda_runtime.h>
#include <cuda_bf16.h>

#define NB 16384
#define DD 2048
#define BQ 64

#define BM 128
#define BN 64
#define BK 64
#define NCHUNK (DD / BK)
#define NSTAGE 4
#define PA 68   // fp32 A stage pitch (floats); 68 % 32 == 4
#define PB 72   // bf16 pitch (elems) for Ab/Bb bufs (R1/R6-proven)

#define STAGE_BYTES (BM * PA * 4)                // 34816
#define ABUF_BYTES (BM * PB * 2)                 // 18432
#define BBUF_BYTES (BN * PB * 2)                 // 9216
#define ABUF_OFF (NSTAGE * STAGE_BYTES)          // 139264
#define BBUF_OFF (ABUF_OFF + 2 * ABUF_BYTES)     // 176128
#define SMEM_BYTES (BBUF_OFF + 2 * BBUF_BYTES)   // 194560

#define NCTA (NB / BM)                           // 128

__device__ float g_pm[NCTA * BQ];   // per-CTA local max (neg logits)
__device__ float g_ps[NCTA * BQ];   // per-CTA sum exp(v - m_loc)
__device__ float g_pp[NCTA * BQ];   // per-CTA pos min
__device__ float g_losspart[BQ];
__device__ unsigned g_cnt = 0;

#define CP_ASYNC16(dst, src)                                                  \
    asm volatile("cp.async.cg.shared.global [%0], [%1], 16;\n" ::"r"(dst),    \
                 "l"(src))
#define CP_COMMIT asm volatile("cp.async.commit_group;\n")
#define CP_WAIT(N) asm volatile("cp.async.wait_group %0;\n" ::"n"(N))

#define LDSM4(r0, r1, r2, r3, addr)                                          \
    asm volatile("ldmatrix.sync.aligned.m8n8.x4.shared.b16 {%0,%1,%2,%3}, [%4];\n" \
                 : "=r"(r0), "=r"(r1), "=r"(r2), "=r"(r3)                    \
                 : "r"(addr))

#define MMA16816(d, a, b0, b1)                                               \
    asm volatile("mma.sync.aligned.m16n8k16.row.col.f32.bf16.bf16.f32 "      \
                 "{%0,%1,%2,%3}, {%4,%5,%6,%7}, {%8,%9}, {%0,%1,%2,%3};\n"   \
                 : "+f"(d[0]), "+f"(d[1]), "+f"(d[2]), "+f"(d[3])            \
                 : "r"(a[0]), "r"(a[1]), "r"(a[2]), "r"(a[3]), "r"(b0), "r"(b1))

// ---------------------------------------------------------------------------
// K1: everything except the final 128-way combine.
//  - bf16 mma via ldmatrix, fp32 accum; convert-ahead single-barrier pipeline
//  - B (f) converted inline from L2 (no prep kernel)
//  - fused streamed copy features -> outF (scalar STG: outF is +4B aligned)
//  - epilogue computes per-CTA loss partials (m, s, pmin) per query
// ---------------------------------------------------------------------------
__global__ __launch_bounds__(256) void gemm_kernel(
    const float* __restrict__ feats,   // [16384, 2048]
    const float* __restrict__ fq,      // [64, 2048]
    const int* __restrict__ labels,    // [16384]
    const int* __restrict__ indexes,   // [64]
    float* __restrict__ outF)          // d_out + 1 (misaligned for float4!)
{
    extern __shared__ __align__(16) char smem[];
    __shared__ int slab[BM];
    __shared__ int sblab[BQ];
    __shared__ float sMx[256], sPn[256], sSm[256];

    const int tid  = threadIdx.x;
    const int lane = tid & 31;
    const int warp = tid >> 5;
    const int wm = warp & 3;   // 4 warps along M (j)
    const int wn = warp >> 2;  // 2 warps along N (b)
    const int rowBase = blockIdx.x * BM;

    const int c4 = tid & 15;   // float4 col within 64-col chunk
    const int r0 = tid >> 4;   // base row (step 16)

    if (tid < BM) slab[tid] = labels[rowBase + tid];
    if (tid < BQ) sblab[tid] = labels[indexes[tid]];

    float acc[2][4][4];
#pragma unroll
    for (int i = 0; i < 2; i++)
#pragma unroll
        for (int j = 0; j < 4; j++)
#pragma unroll
            for (int k = 0; k < 4; k++) acc[i][j][k] = 0.f;

    auto stA  = [&](int s) { return (float*)(smem + s * STAGE_BYTES); };
    auto bufA = [&](int d) {
        return (__nv_bfloat16*)(smem + ABUF_OFF + d * ABUF_BYTES);
    };
    auto bufB = [&](int d) {
        return (__nv_bfloat16*)(smem + BBUF_OFF + d * BBUF_BYTES);
    };

    auto prefetch = [&](int ck) {
        float* A = stA(ck & (NSTAGE - 1));
        const float* src = feats + (size_t)rowBase * DD + ck * BK;
#pragma unroll
        for (int j = 0; j < 8; j++) {
            int r = r0 + 16 * j;
            unsigned d =
                (unsigned)__cvta_generic_to_shared(A + r * PA + c4 * 4);
            CP_ASYNC16(d, src + (size_t)r * DD + c4 * 4);
        }
        CP_COMMIT;
    };

    // B chunk ck: LDG fp32 from L2 (f is hot), convert, store bf16 tile
    auto convertB = [&](int ck) {
        const int row = tid >> 2;      // 0..63 (query b)
        const int cg  = tid & 3;       // 16-col group
        const float* src = fq + (size_t)row * DD + ck * BK + cg * 16;
        float4 a0 = *(const float4*)(src + 0);
        float4 a1 = *(const float4*)(src + 4);
        float4 a2 = *(const float4*)(src + 8);
        float4 a3 = *(const float4*)(src + 12);
        __nv_bfloat16* Bb = bufB(ck & 1);
        uint4 u;
        __nv_bfloat162 h;
        h = __floats2bfloat162_rn(a0.x, a0.y); u.x = *(unsigned*)&h;
        h = __floats2bfloat162_rn(a0.z, a0.w); u.y = *(unsigned*)&h;
        h = __floats2bfloat162_rn(a1.x, a1.y); u.z = *(unsigned*)&h;
        h = __floats2bfloat162_rn(a1.z, a1.w); u.w = *(unsigned*)&h;
        *(uint4*)(Bb + row * PB + cg * 16) = u;
        h = __floats2bfloat162_rn(a2.x, a2.y); u.x = *(unsigned*)&h;
        h = __floats2bfloat162_rn(a2.z, a2.w); u.y = *(unsigned*)&h;
        h = __floats2bfloat162_rn(a3.x, a3.y); u.z = *(unsigned*)&h;
        h = __floats2bfloat162_rn(a3.z, a3.w); u.w = *(unsigned*)&h;
        *(uint4*)(Bb + row * PB + cg * 16 + 8) = u;
    };

    // A chunk ck: fp32 stage -> streamed copy to outF + bf16 Ab buffer
    auto convertA = [&](int ck) {
        const float* A = stA(ck & (NSTAGE - 1));
        __nv_bfloat16* Ab = bufA(ck & 1);
        float* orow = outF + (size_t)rowBase * DD + ck * BK;
#pragma unroll
        for (int j = 0; j < 8; j++) {
            int r = r0 + 16 * j;
            float4 v = *(const float4*)(A + r * PA + c4 * 4);
            float* p = orow + (size_t)r * DD + c4 * 4;
            __stcs(p + 0, v.x);
            __stcs(p + 1, v.y);
            __stcs(p + 2, v.z);
            __stcs(p + 3, v.w);
            __nv_bfloat162 h0 = __floats2bfloat162_rn(v.x, v.y);
            __nv_bfloat162 h1 = __floats2bfloat162_rn(v.z, v.w);
            uint2 u;
            u.x = *(unsigned*)&h0;
            u.y = *(unsigned*)&h1;
            *(uint2*)(Ab + r * PB + c4 * 4) = u;
        }
    };

    const int matid = lane >> 3, mr = lane & 7;

    // prologue
    prefetch(0);
    prefetch(1);
    prefetch(2);
    CP_WAIT(2);          // group 0 complete (this thread)
    __syncthreads();     // ... and all threads
    convertB(0);
    convertA(0);

#pragma unroll 1
    for (int c = 0; c < NCHUNK; c++) {
        if (c + 1 < NCHUNK) {
            if (c + 2 <= NCHUNK - 1) CP_WAIT(1);
            else                     CP_WAIT(0);
        }
        __syncthreads();
        if (c + 3 < NCHUNK) prefetch(c + 3);
        if (c + 1 < NCHUNK) {
            convertB(c + 1);
            convertA(c + 1);
        }

        const __nv_bfloat16* Ab = bufA(c & 1);
        const __nv_bfloat16* Bs = bufB(c & 1);
#pragma unroll
        for (int ks = 0; ks < 4; ks++) {
            unsigned af[2][4], bf2[2][4];
#pragma unroll
            for (int mi = 0; mi < 2; mi++) {
                const __nv_bfloat16* p =
                    Ab + (wm * 32 + mi * 16 + (matid & 1) * 8 + mr) * PB +
                    ks * 16 + (matid >> 1) * 8;
                unsigned ad = (unsigned)__cvta_generic_to_shared(p);
                LDSM4(af[mi][0], af[mi][1], af[mi][2], af[mi][3], ad);
            }
#pragma unroll
            for (int gi = 0; gi < 2; gi++) {
                const __nv_bfloat16* p =
                    Bs + (wn * 32 + gi * 16 + (matid >> 1) * 8 + mr) * PB +
                    ks * 16 + (matid & 1) * 8;
                unsigned ad = (unsigned)__cvta_generic_to_shared(p);
                LDSM4(bf2[gi][0], bf2[gi][1], bf2[gi][2], bf2[gi][3], ad);
            }
#pragma unroll
            for (int mi = 0; mi < 2; mi++)
#pragma unroll
                for (int nt = 0; nt < 4; nt++)
                    MMA16816(acc[mi][nt], af[mi],
                             bf2[nt >> 1][(nt & 1) * 2],
                             bf2[nt >> 1][(nt & 1) * 2 + 1]);
        }
    }

    // epilogue: accums -> smem sC[j][b]
    __syncthreads();
    float* sC = (float*)smem;  // [128][65]
    const int g = lane >> 2, t4 = lane & 3;
#pragma unroll
    for (int mi = 0; mi < 2; mi++)
#pragma unroll
        for (int nt = 0; nt < 4; nt++) {
            int ml = wm * 32 + mi * 16 + g;
            int nn = wn * 32 + nt * 8 + t4 * 2;
            sC[ml * 65 + nn]           = acc[mi][nt][0];
            sC[ml * 65 + nn + 1]       = acc[mi][nt][1];
            sC[(ml + 8) * 65 + nn]     = acc[mi][nt][2];
            sC[(ml + 8) * 65 + nn + 1] = acc[mi][nt][3];
        }
    __syncthreads();

    // per-CTA loss partials: 4 threads per query, 32 rows each
    const float it = 1.0f / 0.07f;
    const int q = tid & 63, kk = tid >> 6;
    const int blab = sblab[q];
    float mneg = -INFINITY, pmin = INFINITY;
#pragma unroll 4
    for (int j = kk * 32; j < kk * 32 + 32; j++) {
        float v = sC[j * 65 + q] * it;
        if (slab[j] != blab) mneg = fmaxf(mneg, v);
        else                 pmin = fminf(pmin, v);
    }
    sMx[tid] = mneg; sPn[tid] = pmin;
    __syncthreads();
    if (tid < 64) {
        float m = fmaxf(fmaxf(sMx[tid], sMx[tid + 64]),
                        fmaxf(sMx[tid + 128], sMx[tid + 192]));
        float p = fminf(fminf(sPn[tid], sPn[tid + 64]),
                        fminf(sPn[tid + 128], sPn[tid + 192]));
        sMx[tid] = m;  // m_cta for query tid
        sPn[tid] = p;
    }
    __syncthreads();
    const float mC = sMx[q];
    const float thr = mC - 25.0f;
    float s = 0.f;
    if (mneg > thr) {  // whole slice below threshold -> skip
#pragma unroll 4
        for (int j = kk * 32; j < kk * 32 + 32; j++) {
            float v = sC[j * 65 + q] * it;
            if (slab[j] != blab && v > thr) s += __expf(v - mC);
        }
    }
    sSm[tid] = s;
    __syncthreads();
    if (tid < 64) {
        float sc = sSm[tid] + sSm[tid + 64] + sSm[tid + 128] + sSm[tid + 192];
        int o = blockIdx.x * BQ + tid;   // [cta][q] -> coalesced write
        g_pm[o] = sMx[tid];
        g_ps[o] = sc;
        g_pp[o] = sPn[tid];
    }
}

// ---------------------------------------------------------------------------
// K2: blocks 0..63   -> combine 128 CTA partials for query bx; last block
//                       (counter) forms the mean loss, writes out[0], resets.
//     blocks 64..127 -> momentum update for batch b = bx - 64.
// ---------------------------------------------------------------------------
__global__ __launch_bounds__(256) void post_kernel(
    const int* __restrict__ indexes,
    const float* __restrict__ feats, const float* __restrict__ fweak,
    float* __restrict__ out)
{
    __shared__ float sA[256], sB[256], sD[256];
    __shared__ int s_last;
    const int bx = blockIdx.x;
    const int tid = threadIdx.x;

    if (bx >= BQ) {
        // ---- momentum update (last duplicate index wins) ----
        const int b = bx - BQ;
        const int idx = indexes[b];
        for (int b2 = b + 1; b2 < BQ; b2++)
            if (indexes[b2] == idx) return;

        float w[8];
        float ssum = 0.f;
        const float* fr = feats + (size_t)idx * DD;
        const float* wr = fweak + (size_t)b * DD;
#pragma unroll
        for (int i = 0; i < 8; i++) {
            int k = i * 256 + tid;
            float v = fr[k] * 0.2f + wr[k] * 0.8f;
            w[i] = v;
            ssum += v * v;
        }
        sA[tid] = ssum;
        __syncthreads();
        for (int o = 128; o > 0; o >>= 1) {
            if (tid < o) sA[tid] += sA[tid + o];
            __syncthreads();
        }
        float inv = 1.0f / fmaxf(sqrtf(sA[0]), 1e-12f);
        float* orow = out + 1 + (size_t)idx * DD;
#pragma unroll
        for (int i = 0; i < 8; i++) orow[i * 256 + tid] = w[i] * inv;
        return;
    }

    // ---- combine partials for query b = bx ----
    const int b = bx;
    float m_t = -INFINITY, s_t = 0.f, p_t = INFINITY;
    if (tid < NCTA) {
        m_t = g_pm[tid * BQ + b];
        s_t = g_ps[tid * BQ + b];
        p_t = g_pp[tid * BQ + b];
    }
    sA[tid] = m_t; sB[tid] = p_t;
    __syncthreads();
    for (int o = 128; o > 0; o >>= 1) {
        if (tid < o) {
            sA[tid] = fmaxf(sA[tid], sA[tid + o]);
            sB[tid] = fminf(sB[tid], sB[tid + o]);
        }
        __syncthreads();
    }
    const float M = sA[0], P = sB[0];
    float contrib = (tid < NCTA && m_t > -INFINITY)
                        ? s_t * __expf(m_t - M)
                        : 0.f;
    sD[tid] = contrib;
    __syncthreads();
    for (int o = 128; o > 0; o >>= 1) {
        if (tid < o) sD[tid] += sD[tid + o];
        __syncthreads();
    }
    if (tid == 0) {
        float S = sD[0];
        float nm = fmaxf(M, P);
        float ns = S * __expf(M - nm) + __expf(P - nm);
        g_losspart[b] = nm + logf(ns) - P;  // lse - logit0
        __threadfence();
        unsigned c = atomicAdd(&g_cnt, 1u);
        s_last = (c == BQ - 1);
    }
    __syncthreads();

    if (s_last) {
        sD[tid] = (tid < BQ) ? *((volatile float*)&g_losspart[tid]) : 0.f;
        __syncthreads();
        for (int o = 128; o > 0; o >>= 1) {
            if (tid < o) sD[tid] += sD[tid + o];
            __syncthreads();
        }
        if (tid == 0) {
            out[0] = sD[0] * (1.0f / 64.0f);
            g_cnt = 0;  // reset for next graph replay
        }
    }
}

// ---------------------------------------------------------------------------
extern "C" void kernel_launch(void* const* d_in, const int* in_sizes, int n_in,
                              void* d_out, int out_size)
{
    const float* fq      = (const float*)d_in[0];  // f        [64,2048]
    const float* fweak   = (const float*)d_in[1];  // f_weak   [64,2048]
    const int*   indexes = (const int*)d_in[2];    // [64]
    const float* feats   = (const float*)d_in[3];  // features [16384,2048]
    const int*   labels  = (const int*)d_in[4];    // [16384]
    float* out = (float*)d_out;                    // [0]=loss, [1:]=features

    cudaFuncSetAttribute(gemm_kernel,
                         cudaFuncAttributeMaxDynamicSharedMemorySize,
                         SMEM_BYTES);

    gemm_kernel<<<NCTA, 256, SMEM_BYTES>>>(feats, fq, labels, indexes,
                                           out + 1);
    post_kernel<<<BQ * 2, 256>>>(indexes, feats, fweak, out);
}